// round 1
// baseline (speedup 1.0000x reference)
#include <cuda_runtime.h>
#include <cstddef>

// ---------------------------------------------------------------------------
// GCN 3-layer encoder.
//   per layer: g = (act(in) @ W) * dinv[row]   (GEMM with row-scale epilogue)
//              out_i = dinv_i * (sum_{e: dst=i} g[src_e] + g_i) + b  [+ReLU]
// CSR (by dst) built per call: histogram -> scan -> scatter. No float atomics.
// ---------------------------------------------------------------------------

#define N_MAX 100000
#define E_MAX 1600000

__device__ float g_buf[(size_t)N_MAX * 128];
__device__ float agg_buf[(size_t)N_MAX * 128];
__device__ float dinv_buf[N_MAX];
__device__ int   deg_buf[N_MAX];
__device__ int   rowptr_buf[N_MAX + 1];
__device__ int   cursor_buf[N_MAX];
__device__ int   csrsrc_buf[E_MAX];

// -------------------------------- CSR prep --------------------------------

__global__ void k_zero_deg(int n) {
    int i = blockIdx.x * blockDim.x + threadIdx.x;
    if (i < n) deg_buf[i] = 0;
}

__global__ void k_hist(const int* __restrict__ dst, int e) {
    int i = blockIdx.x * blockDim.x + threadIdx.x;
    if (i < e) atomicAdd(&deg_buf[dst[i]], 1);
}

__global__ void k_dinv(int n) {
    int i = blockIdx.x * blockDim.x + threadIdx.x;
    if (i < n) dinv_buf[i] = rsqrtf((float)deg_buf[i] + 1.0f);
}

// Single-block exclusive scan over deg -> rowptr (and cursor copy).
__global__ void k_scan(int n, int e) {
    __shared__ int sh[1024];
    __shared__ int carry;
    int t = threadIdx.x;
    if (t == 0) carry = 0;
    __syncthreads();
    for (int base = 0; base < n; base += 1024) {
        int i = base + t;
        int v = (i < n) ? deg_buf[i] : 0;
        sh[t] = v;
        __syncthreads();
        #pragma unroll
        for (int off = 1; off < 1024; off <<= 1) {
            int x = (t >= off) ? sh[t - off] : 0;
            __syncthreads();
            sh[t] += x;
            __syncthreads();
        }
        int excl = sh[t] - v;
        if (i < n) {
            int p = carry + excl;
            rowptr_buf[i] = p;
            cursor_buf[i] = p;
        }
        int tot = sh[1023];
        __syncthreads();
        if (t == 0) carry += tot;
        __syncthreads();
    }
    if (t == 0) rowptr_buf[n] = e;
}

__global__ void k_scatter(const int* __restrict__ src, const int* __restrict__ dst, int e) {
    int i = blockIdx.x * blockDim.x + threadIdx.x;
    if (i < e) {
        int d = dst[i];
        int pos = atomicAdd(&cursor_buf[d], 1);
        csrsrc_buf[pos] = src[i];
    }
}

// -------------------------------- GEMM ------------------------------------
// G[row, :] = (X[row, :] @ W) * dinv[row].   DIN = 128 fixed.
// Block: 256 threads, TR=64 rows. Thread = (cg, rg): 4 cols x RPT rows.

template <int DOUT>
__global__ __launch_bounds__(256) void k_gemm(const float* __restrict__ X,
                                              const float* __restrict__ W,
                                              float* __restrict__ G, int n) {
    constexpr int DIN = 128;
    constexpr int TR = 64;
    constexpr int CG = DOUT / 4;    // col groups (float4 per thread)
    constexpr int RG = 256 / CG;    // row groups
    constexpr int RPT = TR / RG;    // rows per thread
    __shared__ float xs[TR * DIN];

    int t = threadIdx.x;
    int cg = t % CG, rg = t / CG;
    int rowBase = blockIdx.x * TR;

    // Stage x tile (vectorized, zero-pad tail rows).
    const float4* X4 = (const float4*)X;
    float4* xs4 = (float4*)xs;
    #pragma unroll
    for (int i = t; i < TR * (DIN / 4); i += 256) {
        int r = i / (DIN / 4);
        int row = rowBase + r;
        xs4[i] = (row < n) ? X4[(size_t)row * (DIN / 4) + (i % (DIN / 4))]
                           : make_float4(0.f, 0.f, 0.f, 0.f);
    }
    __syncthreads();

    float4 acc[RPT];
    #pragma unroll
    for (int r = 0; r < RPT; r++) acc[r] = make_float4(0.f, 0.f, 0.f, 0.f);

    const float4* W4 = (const float4*)W;
    int r0 = rg * RPT;
    #pragma unroll 4
    for (int k = 0; k < DIN; k++) {
        float4 w = __ldg(&W4[k * CG + cg]);
        #pragma unroll
        for (int r = 0; r < RPT; r++) {
            float xv = xs[(r0 + r) * DIN + k];  // warp-uniform -> broadcast
            acc[r].x += xv * w.x;
            acc[r].y += xv * w.y;
            acc[r].z += xv * w.z;
            acc[r].w += xv * w.w;
        }
    }

    #pragma unroll
    for (int r = 0; r < RPT; r++) {
        int row = rowBase + r0 + r;
        if (row < n) {
            float di = dinv_buf[row];
            float4 o = make_float4(acc[r].x * di, acc[r].y * di,
                                   acc[r].z * di, acc[r].w * di);
            ((float4*)G)[(size_t)row * CG + cg] = o;
        }
    }
}

// ------------------------------ Aggregation --------------------------------
// One warp per node. acc = g_i + sum g[src]; out = acc*dinv_i + b [relu].

template <int D, bool RELU>
__global__ __launch_bounds__(256) void k_aggregate(const float* __restrict__ G,
                                                   const float* __restrict__ bias,
                                                   float* __restrict__ OUT, int n) {
    int wid = (blockIdx.x * blockDim.x + threadIdx.x) >> 5;
    int lane = threadIdx.x & 31;
    if (wid >= n) return;
    constexpr int V = D / 32;  // floats per lane: 4 (D=128) or 2 (D=64)

    float acc[V];
    {
        const float* gi = G + (size_t)wid * D + lane * V;
        if constexpr (V == 4) {
            float4 a = *(const float4*)gi;
            acc[0] = a.x; acc[1] = a.y; acc[2] = a.z; acc[3] = a.w;
        } else {
            float2 a = *(const float2*)gi;
            acc[0] = a.x; acc[1] = a.y;
        }
    }

    int s0 = rowptr_buf[wid];
    int s1 = rowptr_buf[wid + 1];

    int j = s0;
    // Unrolled-by-4 for memory-level parallelism on the gathers.
    for (; j + 3 < s1; j += 4) {
        int sa = __ldg(&csrsrc_buf[j]);
        int sb = __ldg(&csrsrc_buf[j + 1]);
        int sc = __ldg(&csrsrc_buf[j + 2]);
        int sd = __ldg(&csrsrc_buf[j + 3]);
        if constexpr (V == 4) {
            float4 a = __ldg((const float4*)(G + (size_t)sa * D) + lane);
            float4 b = __ldg((const float4*)(G + (size_t)sb * D) + lane);
            float4 c = __ldg((const float4*)(G + (size_t)sc * D) + lane);
            float4 d = __ldg((const float4*)(G + (size_t)sd * D) + lane);
            acc[0] += a.x + b.x + c.x + d.x;
            acc[1] += a.y + b.y + c.y + d.y;
            acc[2] += a.z + b.z + c.z + d.z;
            acc[3] += a.w + b.w + c.w + d.w;
        } else {
            float2 a = __ldg((const float2*)(G + (size_t)sa * D) + lane);
            float2 b = __ldg((const float2*)(G + (size_t)sb * D) + lane);
            float2 c = __ldg((const float2*)(G + (size_t)sc * D) + lane);
            float2 d = __ldg((const float2*)(G + (size_t)sd * D) + lane);
            acc[0] += a.x + b.x + c.x + d.x;
            acc[1] += a.y + b.y + c.y + d.y;
        }
    }
    for (; j < s1; j++) {
        int s = __ldg(&csrsrc_buf[j]);
        if constexpr (V == 4) {
            float4 a = __ldg((const float4*)(G + (size_t)s * D) + lane);
            acc[0] += a.x; acc[1] += a.y; acc[2] += a.z; acc[3] += a.w;
        } else {
            float2 a = __ldg((const float2*)(G + (size_t)s * D) + lane);
            acc[0] += a.x; acc[1] += a.y;
        }
    }

    float di = dinv_buf[wid];
    float* op = OUT + (size_t)wid * D + lane * V;
    if constexpr (V == 4) {
        float4 b = __ldg((const float4*)bias + lane);
        float4 o = make_float4(acc[0] * di + b.x, acc[1] * di + b.y,
                               acc[2] * di + b.z, acc[3] * di + b.w);
        if (RELU) {
            o.x = fmaxf(o.x, 0.f); o.y = fmaxf(o.y, 0.f);
            o.z = fmaxf(o.z, 0.f); o.w = fmaxf(o.w, 0.f);
        }
        *(float4*)op = o;
    } else {
        float2 b = __ldg((const float2*)bias + lane);
        float2 o = make_float2(acc[0] * di + b.x, acc[1] * di + b.y);
        if (RELU) { o.x = fmaxf(o.x, 0.f); o.y = fmaxf(o.y, 0.f); }
        *(float2*)op = o;
    }
}

// ------------------------------- launch ------------------------------------

extern "C" void kernel_launch(void* const* d_in, const int* in_sizes, int n_in,
                              void* d_out, int out_size) {
    const float* x  = (const float*)d_in[0];
    const int*   ei = (const int*)d_in[1];
    const float* W1 = (const float*)d_in[2];
    const float* b1 = (const float*)d_in[3];
    const float* W2 = (const float*)d_in[4];
    const float* b2 = (const float*)d_in[5];
    const float* W3 = (const float*)d_in[6];
    const float* b3 = (const float*)d_in[7];

    int n = in_sizes[0] / 128;
    int e = in_sizes[1] / 2;
    const int* src = ei;
    const int* dst = ei + e;

    float* g;
    float* agg;
    cudaGetSymbolAddress((void**)&g, g_buf);
    cudaGetSymbolAddress((void**)&agg, agg_buf);
    float* out = (float*)d_out;

    int nb = (n + 255) / 256;
    int eb = (e + 255) / 256;

    // CSR prep
    k_zero_deg<<<nb, 256>>>(n);
    k_hist<<<eb, 256>>>(dst, e);
    k_dinv<<<nb, 256>>>(n);
    k_scan<<<1, 1024>>>(n, e);
    k_scatter<<<eb, 256>>>(src, dst, e);

    int gemm_blocks = (n + 63) / 64;
    int agg_blocks128 = (n * 32 + 255) / 256;

    // Layer 1: g = (x@W1)*dinv ; agg = relu(dinv*(sum g)+b1)
    k_gemm<128><<<gemm_blocks, 256>>>(x, W1, g, n);
    k_aggregate<128, true><<<agg_blocks128, 256>>>(g, b1, agg, n);

    // Layer 2
    k_gemm<128><<<gemm_blocks, 256>>>(agg, W2, g, n);
    k_aggregate<128, true><<<agg_blocks128, 256>>>(g, b2, agg, n);

    // Layer 3 (D=64, no relu) -> d_out
    k_gemm<64><<<gemm_blocks, 256>>>(agg, W3, g, n);
    k_aggregate<64, false><<<agg_blocks128, 256>>>(g, b3, out, n);
}

// round 2
// speedup vs baseline: 1.2937x; 1.2937x over previous
#include <cuda_runtime.h>
#include <cstddef>

// ---------------------------------------------------------------------------
// GCN 3-layer encoder.
//   per layer: g = (act(in) @ W) * dinv[row]   (GEMM with row-scale epilogue)
//              out_i = dinv_i * (sum_{e: dst=i} g[src_e] + g_i) + b  [+ReLU]
// CSR (by dst) built per call: histogram -> two-level scan -> scatter.
// ---------------------------------------------------------------------------

#define N_MAX 100000
#define E_MAX 1600000
#define SCAN_B 1024
#define MAX_SCAN_BLOCKS 128   // ceil(100000/1024)=98

__device__ float g_buf[(size_t)N_MAX * 128];
__device__ float agg_buf[(size_t)N_MAX * 128];
__device__ float dinv_buf[N_MAX];
__device__ int   deg_buf[N_MAX];
__device__ int   rowptr_buf[N_MAX + 1];
__device__ int   cursor_buf[N_MAX];
__device__ int   csrsrc_buf[E_MAX];
__device__ int   blocksum_buf[MAX_SCAN_BLOCKS];

// -------------------------------- CSR prep --------------------------------

__global__ void k_zero_deg(int n) {
    int i = blockIdx.x * blockDim.x + threadIdx.x;
    if (i < n) deg_buf[i] = 0;
}

__global__ void k_hist(const int* __restrict__ dst, int e) {
    int i = blockIdx.x * blockDim.x + threadIdx.x;
    if (i < e) atomicAdd(&deg_buf[dst[i]], 1);
}

__global__ void k_dinv(int n) {
    int i = blockIdx.x * blockDim.x + threadIdx.x;
    if (i < n) dinv_buf[i] = rsqrtf((float)deg_buf[i] + 1.0f);
}

// ---- two-level scan: blocksum -> scan sums (1 block) -> per-block scan ----

__global__ __launch_bounds__(SCAN_B) void k_blocksum(int n) {
    __shared__ int wsum[32];
    int i = blockIdx.x * SCAN_B + threadIdx.x;
    int v = (i < n) ? deg_buf[i] : 0;
    #pragma unroll
    for (int off = 16; off > 0; off >>= 1)
        v += __shfl_down_sync(0xffffffffu, v, off);
    int lane = threadIdx.x & 31, w = threadIdx.x >> 5;
    if (lane == 0) wsum[w] = v;
    __syncthreads();
    if (w == 0) {
        int s = wsum[lane];
        #pragma unroll
        for (int off = 16; off > 0; off >>= 1)
            s += __shfl_down_sync(0xffffffffu, s, off);
        if (lane == 0) blocksum_buf[blockIdx.x] = s;
    }
}

// Single block (128 threads), exclusive scan of block sums; also rowptr[n]=e.
__global__ void k_scan_blocksums(int nblocks, int n, int e) {
    __shared__ int wsum[4];
    int t = threadIdx.x;
    int v = (t < nblocks) ? blocksum_buf[t] : 0;
    int lane = t & 31, w = t >> 5;
    // inclusive warp scan
    int s = v;
    #pragma unroll
    for (int off = 1; off < 32; off <<= 1) {
        int x = __shfl_up_sync(0xffffffffu, s, off);
        if (lane >= off) s += x;
    }
    if (lane == 31) wsum[w] = s;
    __syncthreads();
    int base = 0;
    #pragma unroll
    for (int k = 0; k < 4; k++) base += (k < w) ? wsum[k] : 0;
    if (t < nblocks) blocksum_buf[t] = base + s - v;  // exclusive
    if (t == 0) rowptr_buf[n] = e;
}

__global__ __launch_bounds__(SCAN_B) void k_block_scan(int n) {
    __shared__ int wsum[32];
    int i = blockIdx.x * SCAN_B + threadIdx.x;
    int v = (i < n) ? deg_buf[i] : 0;
    int lane = threadIdx.x & 31, w = threadIdx.x >> 5;
    // inclusive warp scan
    int s = v;
    #pragma unroll
    for (int off = 1; off < 32; off <<= 1) {
        int x = __shfl_up_sync(0xffffffffu, s, off);
        if (lane >= off) s += x;
    }
    if (lane == 31) wsum[w] = s;
    __syncthreads();
    if (w == 0) {
        int ws = wsum[lane];
        #pragma unroll
        for (int off = 1; off < 32; off <<= 1) {
            int x = __shfl_up_sync(0xffffffffu, ws, off);
            if (lane >= off) ws += x;
        }
        wsum[lane] = ws;
    }
    __syncthreads();
    int warpBase = (w > 0) ? wsum[w - 1] : 0;
    if (i < n) {
        int p = blocksum_buf[blockIdx.x] + warpBase + (s - v);  // exclusive
        rowptr_buf[i] = p;
        cursor_buf[i] = p;
    }
}

__global__ void k_scatter(const int* __restrict__ src, const int* __restrict__ dst, int e) {
    int i = blockIdx.x * blockDim.x + threadIdx.x;
    if (i < e) {
        int d = dst[i];
        int pos = atomicAdd(&cursor_buf[d], 1);
        csrsrc_buf[pos] = src[i];
    }
}

// -------------------------------- GEMM ------------------------------------
// G[row, :] = (X[row, :] @ W) * dinv[row].   DIN = 128 fixed.
// Block: 256 threads, TR=64 rows. Thread = (cg, rg): 4 cols x RPT rows.

template <int DOUT>
__global__ __launch_bounds__(256) void k_gemm(const float* __restrict__ X,
                                              const float* __restrict__ W,
                                              float* __restrict__ G, int n) {
    constexpr int DIN = 128;
    constexpr int TR = 64;
    constexpr int CG = DOUT / 4;    // col groups (float4 per thread)
    constexpr int RG = 256 / CG;    // row groups
    constexpr int RPT = TR / RG;    // rows per thread
    __shared__ float xs[TR * DIN];

    int t = threadIdx.x;
    int cg = t % CG, rg = t / CG;
    int rowBase = blockIdx.x * TR;

    const float4* X4 = (const float4*)X;
    float4* xs4 = (float4*)xs;
    #pragma unroll
    for (int i = t; i < TR * (DIN / 4); i += 256) {
        int r = i / (DIN / 4);
        int row = rowBase + r;
        xs4[i] = (row < n) ? X4[(size_t)row * (DIN / 4) + (i % (DIN / 4))]
                           : make_float4(0.f, 0.f, 0.f, 0.f);
    }
    __syncthreads();

    float4 acc[RPT];
    #pragma unroll
    for (int r = 0; r < RPT; r++) acc[r] = make_float4(0.f, 0.f, 0.f, 0.f);

    const float4* W4 = (const float4*)W;
    int r0 = rg * RPT;
    #pragma unroll 4
    for (int k = 0; k < DIN; k++) {
        float4 w = __ldg(&W4[k * CG + cg]);
        #pragma unroll
        for (int r = 0; r < RPT; r++) {
            float xv = xs[(r0 + r) * DIN + k];  // warp-uniform -> broadcast
            acc[r].x += xv * w.x;
            acc[r].y += xv * w.y;
            acc[r].z += xv * w.z;
            acc[r].w += xv * w.w;
        }
    }

    #pragma unroll
    for (int r = 0; r < RPT; r++) {
        int row = rowBase + r0 + r;
        if (row < n) {
            float di = dinv_buf[row];
            float4 o = make_float4(acc[r].x * di, acc[r].y * di,
                                   acc[r].z * di, acc[r].w * di);
            ((float4*)G)[(size_t)row * CG + cg] = o;
        }
    }
}

// ------------------------------ Aggregation --------------------------------
// One warp per node. acc = g_i + sum g[src]; out = acc*dinv_i + b [relu].

template <int D, bool RELU>
__global__ __launch_bounds__(256) void k_aggregate(const float* __restrict__ G,
                                                   const float* __restrict__ bias,
                                                   float* __restrict__ OUT, int n) {
    int wid = (blockIdx.x * blockDim.x + threadIdx.x) >> 5;
    int lane = threadIdx.x & 31;
    if (wid >= n) return;
    constexpr int V = D / 32;  // floats per lane: 4 (D=128) or 2 (D=64)

    float acc[V];
    {
        const float* gi = G + (size_t)wid * D + lane * V;
        if constexpr (V == 4) {
            float4 a = *(const float4*)gi;
            acc[0] = a.x; acc[1] = a.y; acc[2] = a.z; acc[3] = a.w;
        } else {
            float2 a = *(const float2*)gi;
            acc[0] = a.x; acc[1] = a.y;
        }
    }

    int s0 = rowptr_buf[wid];
    int s1 = rowptr_buf[wid + 1];

    int j = s0;
    for (; j + 3 < s1; j += 4) {
        int sa = __ldg(&csrsrc_buf[j]);
        int sb = __ldg(&csrsrc_buf[j + 1]);
        int sc = __ldg(&csrsrc_buf[j + 2]);
        int sd = __ldg(&csrsrc_buf[j + 3]);
        if constexpr (V == 4) {
            float4 a = __ldg((const float4*)(G + (size_t)sa * D) + lane);
            float4 b = __ldg((const float4*)(G + (size_t)sb * D) + lane);
            float4 c = __ldg((const float4*)(G + (size_t)sc * D) + lane);
            float4 d = __ldg((const float4*)(G + (size_t)sd * D) + lane);
            acc[0] += a.x + b.x + c.x + d.x;
            acc[1] += a.y + b.y + c.y + d.y;
            acc[2] += a.z + b.z + c.z + d.z;
            acc[3] += a.w + b.w + c.w + d.w;
        } else {
            float2 a = __ldg((const float2*)(G + (size_t)sa * D) + lane);
            float2 b = __ldg((const float2*)(G + (size_t)sb * D) + lane);
            float2 c = __ldg((const float2*)(G + (size_t)sc * D) + lane);
            float2 d = __ldg((const float2*)(G + (size_t)sd * D) + lane);
            acc[0] += a.x + b.x + c.x + d.x;
            acc[1] += a.y + b.y + c.y + d.y;
        }
    }
    for (; j < s1; j++) {
        int s = __ldg(&csrsrc_buf[j]);
        if constexpr (V == 4) {
            float4 a = __ldg((const float4*)(G + (size_t)s * D) + lane);
            acc[0] += a.x; acc[1] += a.y; acc[2] += a.z; acc[3] += a.w;
        } else {
            float2 a = __ldg((const float2*)(G + (size_t)s * D) + lane);
            acc[0] += a.x; acc[1] += a.y;
        }
    }

    float di = dinv_buf[wid];
    float* op = OUT + (size_t)wid * D + lane * V;
    if constexpr (V == 4) {
        float4 b = __ldg((const float4*)bias + lane);
        float4 o = make_float4(acc[0] * di + b.x, acc[1] * di + b.y,
                               acc[2] * di + b.z, acc[3] * di + b.w);
        if (RELU) {
            o.x = fmaxf(o.x, 0.f); o.y = fmaxf(o.y, 0.f);
            o.z = fmaxf(o.z, 0.f); o.w = fmaxf(o.w, 0.f);
        }
        *(float4*)op = o;
    } else {
        float2 b = __ldg((const float2*)bias + lane);
        float2 o = make_float2(acc[0] * di + b.x, acc[1] * di + b.y);
        if (RELU) { o.x = fmaxf(o.x, 0.f); o.y = fmaxf(o.y, 0.f); }
        *(float2*)op = o;
    }
}

// ------------------------------- launch ------------------------------------

extern "C" void kernel_launch(void* const* d_in, const int* in_sizes, int n_in,
                              void* d_out, int out_size) {
    const float* x  = (const float*)d_in[0];
    const int*   ei = (const int*)d_in[1];
    const float* W1 = (const float*)d_in[2];
    const float* b1 = (const float*)d_in[3];
    const float* W2 = (const float*)d_in[4];
    const float* b2 = (const float*)d_in[5];
    const float* W3 = (const float*)d_in[6];
    const float* b3 = (const float*)d_in[7];

    int n = in_sizes[0] / 128;
    int e = in_sizes[1] / 2;
    const int* src = ei;
    const int* dst = ei + e;

    float* g;
    float* agg;
    cudaGetSymbolAddress((void**)&g, g_buf);
    cudaGetSymbolAddress((void**)&agg, agg_buf);
    float* out = (float*)d_out;

    int nb = (n + 255) / 256;
    int eb = (e + 255) / 256;
    int scan_blocks = (n + SCAN_B - 1) / SCAN_B;

    // CSR prep
    k_zero_deg<<<nb, 256>>>(n);
    k_hist<<<eb, 256>>>(dst, e);
    k_dinv<<<nb, 256>>>(n);
    k_blocksum<<<scan_blocks, SCAN_B>>>(n);
    k_scan_blocksums<<<1, MAX_SCAN_BLOCKS>>>(scan_blocks, n, e);
    k_block_scan<<<scan_blocks, SCAN_B>>>(n);
    k_scatter<<<eb, 256>>>(src, dst, e);

    int gemm_blocks = (n + 63) / 64;
    int agg_blocks128 = (n * 32 + 255) / 256;

    // Layer 1
    k_gemm<128><<<gemm_blocks, 256>>>(x, W1, g, n);
    k_aggregate<128, true><<<agg_blocks128, 256>>>(g, b1, agg, n);

    // Layer 2
    k_gemm<128><<<gemm_blocks, 256>>>(agg, W2, g, n);
    k_aggregate<128, true><<<agg_blocks128, 256>>>(g, b2, agg, n);

    // Layer 3 (D=64, no relu) -> d_out
    k_gemm<64><<<gemm_blocks, 256>>>(agg, W3, g, n);
    k_aggregate<64, false><<<agg_blocks128, 256>>>(g, b3, out, n);
}

// round 3
// speedup vs baseline: 1.9652x; 1.5190x over previous
#include <cuda_runtime.h>
#include <cstddef>
#include <cstdint>

// ---------------------------------------------------------------------------
// GCN 3-layer encoder.
//   per layer: g = (act(in) @ W) * dinv[row]   (tf32 tensor-core GEMM)
//              out_i = dinv_i * (sum_{e: dst=i} g[src_e] + g_i) + b  [+ReLU]
// CSR (by dst) built per call: histogram -> two-level scan -> scatter.
// ---------------------------------------------------------------------------

#define N_MAX 100000
#define E_MAX 1600000
#define SCAN_B 1024
#define MAX_SCAN_BLOCKS 128

__device__ float g_buf[(size_t)N_MAX * 128];
__device__ float agg_buf[(size_t)N_MAX * 128];
__device__ float dinv_buf[N_MAX];
__device__ int   deg_buf[N_MAX];
__device__ int   rowptr_buf[N_MAX + 1];
__device__ int   cursor_buf[N_MAX];
__device__ int   csrsrc_buf[E_MAX];
__device__ int   blocksum_buf[MAX_SCAN_BLOCKS];

// -------------------------------- CSR prep --------------------------------

__global__ void k_zero_deg(int n) {
    int i = blockIdx.x * blockDim.x + threadIdx.x;
    if (i < n) deg_buf[i] = 0;
}

__global__ void k_hist(const int* __restrict__ dst, int e) {
    int i = blockIdx.x * blockDim.x + threadIdx.x;
    if (i < e) atomicAdd(&deg_buf[dst[i]], 1);
}

__global__ void k_dinv(int n) {
    int i = blockIdx.x * blockDim.x + threadIdx.x;
    if (i < n) dinv_buf[i] = rsqrtf((float)deg_buf[i] + 1.0f);
}

__global__ __launch_bounds__(SCAN_B) void k_blocksum(int n) {
    __shared__ int wsum[32];
    int i = blockIdx.x * SCAN_B + threadIdx.x;
    int v = (i < n) ? deg_buf[i] : 0;
    #pragma unroll
    for (int off = 16; off > 0; off >>= 1)
        v += __shfl_down_sync(0xffffffffu, v, off);
    int lane = threadIdx.x & 31, w = threadIdx.x >> 5;
    if (lane == 0) wsum[w] = v;
    __syncthreads();
    if (w == 0) {
        int s = wsum[lane];
        #pragma unroll
        for (int off = 16; off > 0; off >>= 1)
            s += __shfl_down_sync(0xffffffffu, s, off);
        if (lane == 0) blocksum_buf[blockIdx.x] = s;
    }
}

__global__ void k_scan_blocksums(int nblocks, int n, int e) {
    __shared__ int wsum[4];
    int t = threadIdx.x;
    int v = (t < nblocks) ? blocksum_buf[t] : 0;
    int lane = t & 31, w = t >> 5;
    int s = v;
    #pragma unroll
    for (int off = 1; off < 32; off <<= 1) {
        int x = __shfl_up_sync(0xffffffffu, s, off);
        if (lane >= off) s += x;
    }
    if (lane == 31) wsum[w] = s;
    __syncthreads();
    int base = 0;
    #pragma unroll
    for (int k = 0; k < 4; k++) base += (k < w) ? wsum[k] : 0;
    if (t < nblocks) blocksum_buf[t] = base + s - v;
    if (t == 0) rowptr_buf[n] = e;
}

__global__ __launch_bounds__(SCAN_B) void k_block_scan(int n) {
    __shared__ int wsum[32];
    int i = blockIdx.x * SCAN_B + threadIdx.x;
    int v = (i < n) ? deg_buf[i] : 0;
    int lane = threadIdx.x & 31, w = threadIdx.x >> 5;
    int s = v;
    #pragma unroll
    for (int off = 1; off < 32; off <<= 1) {
        int x = __shfl_up_sync(0xffffffffu, s, off);
        if (lane >= off) s += x;
    }
    if (lane == 31) wsum[w] = s;
    __syncthreads();
    if (w == 0) {
        int ws = wsum[lane];
        #pragma unroll
        for (int off = 1; off < 32; off <<= 1) {
            int x = __shfl_up_sync(0xffffffffu, ws, off);
            if (lane >= off) ws += x;
        }
        wsum[lane] = ws;
    }
    __syncthreads();
    int warpBase = (w > 0) ? wsum[w - 1] : 0;
    if (i < n) {
        int p = blocksum_buf[blockIdx.x] + warpBase + (s - v);
        rowptr_buf[i] = p;
        cursor_buf[i] = p;
    }
}

__global__ void k_scatter(const int* __restrict__ src, const int* __restrict__ dst, int e) {
    int i = blockIdx.x * blockDim.x + threadIdx.x;
    if (i < e) {
        int d = dst[i];
        int pos = atomicAdd(&cursor_buf[d], 1);
        csrsrc_buf[pos] = src[i];
    }
}

// ----------------------- tf32 tensor-core GEMM -----------------------------
// G = (X @ W) * dinv[row].   DIN=128.  Warp tile 32x32 via mma.m16n8k8.tf32.
// 256 threads = 8 warps: WN = DOUT/32 warps along N, WM = 8/WN along M.

__device__ __forceinline__ uint32_t f2tf32(float f) {
    uint32_t u;
    asm("cvt.rna.tf32.f32 %0, %1;" : "=r"(u) : "f"(f));
    return u;
}

template <int DOUT>
__global__ __launch_bounds__(256) void k_gemm_tc(const float* __restrict__ X,
                                                 const float* __restrict__ W,
                                                 float* __restrict__ G, int n) {
    constexpr int DIN = 128;
    constexpr int WN = DOUT / 32;   // 4 (DOUT=128) or 2 (DOUT=64)
    constexpr int WM = 8 / WN;      // 2 or 4
    constexpr int MB = WM * 32;     // 64 or 128 rows per block
    constexpr int XS = DIN + 4;     // padded X stride (floats)
    constexpr int WS = DOUT + 8;    // padded W stride (floats)

    extern __shared__ uint32_t smem[];
    uint32_t* Xs = smem;                 // MB * XS
    uint32_t* Ws = smem + MB * XS;       // DIN * WS

    int t = threadIdx.x;
    int warp = t >> 5, lane = t & 31;
    int wm = warp / WN, wn = warp % WN;
    int g = lane >> 2, tg = lane & 3;
    int rowBase = blockIdx.x * MB;

    // Stage W (cvt to tf32).
    #pragma unroll
    for (int i = t * 4; i < DIN * DOUT; i += 1024) {
        int k = i / DOUT, c = i % DOUT;
        float4 w = __ldg((const float4*)(W + i));
        uint4 u = make_uint4(f2tf32(w.x), f2tf32(w.y), f2tf32(w.z), f2tf32(w.w));
        *(uint4*)&Ws[k * WS + c] = u;
    }
    // Stage X tile (cvt to tf32, zero-pad tail rows).
    #pragma unroll
    for (int i = t * 4; i < MB * DIN; i += 1024) {
        int r = i / DIN, c = i % DIN;
        int row = rowBase + r;
        float4 xv = (row < n) ? __ldg((const float4*)(X + (size_t)row * DIN + c))
                              : make_float4(0.f, 0.f, 0.f, 0.f);
        uint4 u = make_uint4(f2tf32(xv.x), f2tf32(xv.y), f2tf32(xv.z), f2tf32(xv.w));
        *(uint4*)&Xs[r * XS + c] = u;
    }
    __syncthreads();

    float acc[2][4][4];
    #pragma unroll
    for (int a = 0; a < 2; a++)
        #pragma unroll
        for (int u = 0; u < 4; u++)
            #pragma unroll
            for (int k = 0; k < 4; k++) acc[a][u][k] = 0.f;

    #pragma unroll
    for (int ks = 0; ks < DIN / 8; ks++) {
        int k0 = ks * 8;
        uint32_t a[2][4], b[4][2];
        #pragma unroll
        for (int tt = 0; tt < 2; tt++) {
            int r = wm * 32 + tt * 16;
            a[tt][0] = Xs[(r + g) * XS + k0 + tg];
            a[tt][1] = Xs[(r + g + 8) * XS + k0 + tg];
            a[tt][2] = Xs[(r + g) * XS + k0 + tg + 4];
            a[tt][3] = Xs[(r + g + 8) * XS + k0 + tg + 4];
        }
        #pragma unroll
        for (int u = 0; u < 4; u++) {
            int c = wn * 32 + u * 8 + g;
            b[u][0] = Ws[(k0 + tg) * WS + c];
            b[u][1] = Ws[(k0 + tg + 4) * WS + c];
        }
        #pragma unroll
        for (int tt = 0; tt < 2; tt++)
            #pragma unroll
            for (int u = 0; u < 4; u++) {
                asm volatile(
                    "mma.sync.aligned.m16n8k8.row.col.f32.tf32.tf32.f32 "
                    "{%0,%1,%2,%3}, {%4,%5,%6,%7}, {%8,%9}, {%0,%1,%2,%3};"
                    : "+f"(acc[tt][u][0]), "+f"(acc[tt][u][1]),
                      "+f"(acc[tt][u][2]), "+f"(acc[tt][u][3])
                    : "r"(a[tt][0]), "r"(a[tt][1]), "r"(a[tt][2]), "r"(a[tt][3]),
                      "r"(b[u][0]), "r"(b[u][1]));
            }
    }

    // Epilogue: scale by dinv[row], store.
    #pragma unroll
    for (int tt = 0; tt < 2; tt++) {
        int r0 = rowBase + wm * 32 + tt * 16 + g;
        int r1 = r0 + 8;
        int cbase = wn * 32 + 2 * tg;
        if (r0 < n) {
            float di = dinv_buf[r0];
            #pragma unroll
            for (int u = 0; u < 4; u++) {
                float2 o = make_float2(acc[tt][u][0] * di, acc[tt][u][1] * di);
                *(float2*)(G + (size_t)r0 * DOUT + cbase + u * 8) = o;
            }
        }
        if (r1 < n) {
            float di = dinv_buf[r1];
            #pragma unroll
            for (int u = 0; u < 4; u++) {
                float2 o = make_float2(acc[tt][u][2] * di, acc[tt][u][3] * di);
                *(float2*)(G + (size_t)r1 * DOUT + cbase + u * 8) = o;
            }
        }
    }
}

// ------------------------------ Aggregation --------------------------------

template <int D, bool RELU>
__global__ __launch_bounds__(256) void k_aggregate(const float* __restrict__ G,
                                                   const float* __restrict__ bias,
                                                   float* __restrict__ OUT, int n) {
    int wid = (blockIdx.x * blockDim.x + threadIdx.x) >> 5;
    int lane = threadIdx.x & 31;
    if (wid >= n) return;
    constexpr int V = D / 32;

    float acc[V];
    {
        const float* gi = G + (size_t)wid * D + lane * V;
        if constexpr (V == 4) {
            float4 a = *(const float4*)gi;
            acc[0] = a.x; acc[1] = a.y; acc[2] = a.z; acc[3] = a.w;
        } else {
            float2 a = *(const float2*)gi;
            acc[0] = a.x; acc[1] = a.y;
        }
    }

    int s0 = rowptr_buf[wid];
    int s1 = rowptr_buf[wid + 1];

    int j = s0;
    for (; j + 3 < s1; j += 4) {
        int sa = __ldg(&csrsrc_buf[j]);
        int sb = __ldg(&csrsrc_buf[j + 1]);
        int sc = __ldg(&csrsrc_buf[j + 2]);
        int sd = __ldg(&csrsrc_buf[j + 3]);
        if constexpr (V == 4) {
            float4 a = __ldg((const float4*)(G + (size_t)sa * D) + lane);
            float4 b = __ldg((const float4*)(G + (size_t)sb * D) + lane);
            float4 c = __ldg((const float4*)(G + (size_t)sc * D) + lane);
            float4 d = __ldg((const float4*)(G + (size_t)sd * D) + lane);
            acc[0] += a.x + b.x + c.x + d.x;
            acc[1] += a.y + b.y + c.y + d.y;
            acc[2] += a.z + b.z + c.z + d.z;
            acc[3] += a.w + b.w + c.w + d.w;
        } else {
            float2 a = __ldg((const float2*)(G + (size_t)sa * D) + lane);
            float2 b = __ldg((const float2*)(G + (size_t)sb * D) + lane);
            float2 c = __ldg((const float2*)(G + (size_t)sc * D) + lane);
            float2 d = __ldg((const float2*)(G + (size_t)sd * D) + lane);
            acc[0] += a.x + b.x + c.x + d.x;
            acc[1] += a.y + b.y + c.y + d.y;
        }
    }
    for (; j < s1; j++) {
        int s = __ldg(&csrsrc_buf[j]);
        if constexpr (V == 4) {
            float4 a = __ldg((const float4*)(G + (size_t)s * D) + lane);
            acc[0] += a.x; acc[1] += a.y; acc[2] += a.z; acc[3] += a.w;
        } else {
            float2 a = __ldg((const float2*)(G + (size_t)s * D) + lane);
            acc[0] += a.x; acc[1] += a.y;
        }
    }

    float di = dinv_buf[wid];
    float* op = OUT + (size_t)wid * D + lane * V;
    if constexpr (V == 4) {
        float4 b = __ldg((const float4*)bias + lane);
        float4 o = make_float4(acc[0] * di + b.x, acc[1] * di + b.y,
                               acc[2] * di + b.z, acc[3] * di + b.w);
        if (RELU) {
            o.x = fmaxf(o.x, 0.f); o.y = fmaxf(o.y, 0.f);
            o.z = fmaxf(o.z, 0.f); o.w = fmaxf(o.w, 0.f);
        }
        *(float4*)op = o;
    } else {
        float2 b = __ldg((const float2*)bias + lane);
        float2 o = make_float2(acc[0] * di + b.x, acc[1] * di + b.y);
        if (RELU) { o.x = fmaxf(o.x, 0.f); o.y = fmaxf(o.y, 0.f); }
        *(float2*)op = o;
    }
}

// ------------------------------- launch ------------------------------------

extern "C" void kernel_launch(void* const* d_in, const int* in_sizes, int n_in,
                              void* d_out, int out_size) {
    const float* x  = (const float*)d_in[0];
    const int*   ei = (const int*)d_in[1];
    const float* W1 = (const float*)d_in[2];
    const float* b1 = (const float*)d_in[3];
    const float* W2 = (const float*)d_in[4];
    const float* b2 = (const float*)d_in[5];
    const float* W3 = (const float*)d_in[6];
    const float* b3 = (const float*)d_in[7];

    int n = in_sizes[0] / 128;
    int e = in_sizes[1] / 2;
    const int* src = ei;
    const int* dst = ei + e;

    float* g;
    float* agg;
    cudaGetSymbolAddress((void**)&g, g_buf);
    cudaGetSymbolAddress((void**)&agg, agg_buf);
    float* out = (float*)d_out;

    int nb = (n + 255) / 256;
    int eb = (e + 255) / 256;
    int scan_blocks = (n + SCAN_B - 1) / SCAN_B;

    // Dynamic smem sizes for the tensor-core GEMMs.
    constexpr int SMEM128 = (64 * (128 + 4) + 128 * (128 + 8)) * 4;   // 103424
    constexpr int SMEM64  = (128 * (128 + 4) + 128 * (64 + 8)) * 4;   // 104448
    static bool attr_set = false;
    if (!attr_set) {
        cudaFuncSetAttribute(k_gemm_tc<128>, cudaFuncAttributeMaxDynamicSharedMemorySize, SMEM128);
        cudaFuncSetAttribute(k_gemm_tc<64>,  cudaFuncAttributeMaxDynamicSharedMemorySize, SMEM64);
        attr_set = true;
    }

    // CSR prep + layer-1 GEMM ordered so the GEMM is the 4th launch (profiler
    // captures launch #4): gemm1 depends only on dinv.
    k_zero_deg<<<nb, 256>>>(n);
    k_hist<<<eb, 256>>>(dst, e);
    k_dinv<<<nb, 256>>>(n);
    k_gemm_tc<128><<<(n + 63) / 64, 256, SMEM128>>>(x, W1, g, n);      // launch 4
    k_blocksum<<<scan_blocks, SCAN_B>>>(n);
    k_scan_blocksums<<<1, MAX_SCAN_BLOCKS>>>(scan_blocks, n, e);
    k_block_scan<<<scan_blocks, SCAN_B>>>(n);
    k_scatter<<<eb, 256>>>(src, dst, e);

    int agg_blocks = (n * 32 + 255) / 256;

    // Layer 1 aggregation
    k_aggregate<128, true><<<agg_blocks, 256>>>(g, b1, agg, n);

    // Layer 2
    k_gemm_tc<128><<<(n + 63) / 64, 256, SMEM128>>>(agg, W2, g, n);
    k_aggregate<128, true><<<agg_blocks, 256>>>(g, b2, agg, n);

    // Layer 3 (D=64, no relu) -> d_out
    k_gemm_tc<64><<<(n + 127) / 128, 256, SMEM64>>>(agg, W3, g, n);
    k_aggregate<64, false><<<agg_blocks, 256>>>(g, b3, out, n);
}